// round 8
// baseline (speedup 1.0000x reference)
#include <cuda_runtime.h>

#define N_NODES 1048576
#define N_EDGES (4 * N_NODES)

typedef unsigned long long u64;

// Scratch accumulator: per-node (sum0,sum1,sum2,count). Zero-initialized at
// module load; node_kernel re-zeros after consuming (deterministic per call).
__device__ float4 g_scr[N_NODES];
// Padded x table: one 16B row per node -> single-wavefront gathers.
__device__ float4 g_x4[N_NODES];

__device__ __forceinline__ u64 fma2(u64 a, u64 b, u64 c) {
    u64 d;
    asm("fma.rn.f32x2 %0, %1, %2, %3;" : "=l"(d) : "l"(a), "l"(b), "l"(c));
    return d;
}
__device__ __forceinline__ u64 mul2(u64 a, u64 b) {
    u64 d;
    asm("mul.rn.f32x2 %0, %1, %2;" : "=l"(d) : "l"(a), "l"(b));
    return d;
}
__device__ __forceinline__ u64 add2(u64 a, u64 b) {
    u64 d;
    asm("add.rn.f32x2 %0, %1, %2;" : "=l"(d) : "l"(a), "l"(b));
    return d;
}
__device__ __forceinline__ u64 pack2(float lo, float hi) {
    u64 d;
    asm("mov.b64 %0, {%1, %2};" : "=l"(d) : "f"(lo), "f"(hi));
    return d;
}
__device__ __forceinline__ void unpack2(u64 a, float& lo, float& hi) {
    asm("mov.b64 {%0, %1}, %2;" : "=f"(lo), "=f"(hi) : "l"(a));
}
__device__ __forceinline__ u64 relu2(u64 a) {
    float lo, hi;
    unpack2(a, lo, hi);
    return pack2(fmaxf(lo, 0.f), fmaxf(hi, 0.f));
}

// Pad x[N,3] -> g_x4 via smem transpose. One node per thread.
__global__ void __launch_bounds__(256) prep_kernel(const float4* __restrict__ x) {
    __shared__ float sx[768];
    int t = threadIdx.x;
    if (t < 192) {
        float4 v = x[blockIdx.x * 192 + t];
        *(float4*)&sx[4 * t] = v;
    }
    __syncthreads();
    int node = blockIdx.x * 256 + t;
    // stride-3 float reads: 3 coprime to 32 banks -> conflict-free
    g_x4[node] = make_float4(sx[3 * t], sx[3 * t + 1], sx[3 * t + 2], 0.f);
}

// Edge MLP + scatter-add. FOUR edges per thread, two packed f32x2 streams.
__global__ void __launch_bounds__(256) edge_kernel(
        const int*   __restrict__ ei,
        const float* __restrict__ eattr,
        const float* __restrict__ w1a,
        const float* __restrict__ b1a,
        const float* __restrict__ w1b,
        const float* __restrict__ b1b) {
    // per hidden j: [wx, wy, wz, ww, bias, v0, v1, v2], each scalar duplicated.
    __shared__ __align__(16) u64 sw[20][8];
    int t = threadIdx.x;
    if (t < 20) {
        sw[t][0] = pack2(w1a[t],          w1a[t]);
        sw[t][1] = pack2(w1a[20 + t],     w1a[20 + t]);
        sw[t][2] = pack2(w1a[40 + t],     w1a[40 + t]);
        sw[t][3] = pack2(w1a[60 + t],     w1a[60 + t]);
        sw[t][4] = pack2(b1a[t],          b1a[t]);
        sw[t][5] = pack2(w1b[3 * t],      w1b[3 * t]);
        sw[t][6] = pack2(w1b[3 * t + 1],  w1b[3 * t + 1]);
        sw[t][7] = pack2(w1b[3 * t + 2],  w1b[3 * t + 2]);
    }
    __syncthreads();

    int e = (blockIdx.x * 256 + t) * 4;
    if (e >= N_EDGES) return;

    int4   rr = *(const int4*)(ei + e);             // source nodes A,B,C,D
    int4   cc = *(const int4*)(ei + N_EDGES + e);   // destination nodes
    float4 ef = *(const float4*)(eattr + e);

    // 4 single-wavefront gathers issued back-to-back.
    float4 xa = __ldg(&g_x4[rr.x]);
    float4 xb = __ldg(&g_x4[rr.y]);
    float4 xc = __ldg(&g_x4[rr.z]);
    float4 xd = __ldg(&g_x4[rr.w]);

    u64 X0ab = pack2(xa.x, xb.x), X0cd = pack2(xc.x, xd.x);
    u64 X1ab = pack2(xa.y, xb.y), X1cd = pack2(xc.y, xd.y);
    u64 X2ab = pack2(xa.z, xb.z), X2cd = pack2(xc.z, xd.z);
    u64 EAab = pack2(ef.x, ef.y), EAcd = pack2(ef.z, ef.w);

    float bb0 = b1b[0], bb1 = b1b[1], bb2 = b1b[2];
    u64 o0ab = pack2(bb0, bb0), o0cd = o0ab;
    u64 o1ab = pack2(bb1, bb1), o1cd = o1ab;
    u64 o2ab = pack2(bb2, bb2), o2cd = o2ab;

#pragma unroll
    for (int j = 0; j < 20; j++) {
        const u64* w = sw[j];
        // tree-form h: two parallel depth-2 branches + one add
        u64 t1ab = fma2(X0ab, w[0], fma2(X1ab, w[1], w[4]));
        u64 t2ab = fma2(EAab, w[3], mul2(X2ab, w[2]));
        u64 t1cd = fma2(X0cd, w[0], fma2(X1cd, w[1], w[4]));
        u64 t2cd = fma2(EAcd, w[3], mul2(X2cd, w[2]));
        u64 hab = relu2(add2(t1ab, t2ab));
        u64 hcd = relu2(add2(t1cd, t2cd));
        o0ab = fma2(hab, w[5], o0ab);  o0cd = fma2(hcd, w[5], o0cd);
        o1ab = fma2(hab, w[6], o1ab);  o1cd = fma2(hcd, w[6], o1cd);
        o2ab = fma2(hab, w[7], o2ab);  o2cd = fma2(hcd, w[7], o2cd);
    }

    float pA0, pB0, pA1, pB1, pA2, pB2;
    float pC0, pD0, pC1, pD1, pC2, pD2;
    unpack2(o0ab, pA0, pB0); unpack2(o1ab, pA1, pB1); unpack2(o2ab, pA2, pB2);
    unpack2(o0cd, pC0, pD0); unpack2(o1cd, pC1, pD1); unpack2(o2cd, pC2, pD2);

    asm volatile("red.global.add.v4.f32 [%0], {%1, %2, %3, %4};"
                 :: "l"(g_scr + cc.x), "f"(pA0), "f"(pA1), "f"(pA2), "f"(1.0f) : "memory");
    asm volatile("red.global.add.v4.f32 [%0], {%1, %2, %3, %4};"
                 :: "l"(g_scr + cc.y), "f"(pB0), "f"(pB1), "f"(pB2), "f"(1.0f) : "memory");
    asm volatile("red.global.add.v4.f32 [%0], {%1, %2, %3, %4};"
                 :: "l"(g_scr + cc.z), "f"(pC0), "f"(pC1), "f"(pC2), "f"(1.0f) : "memory");
    asm volatile("red.global.add.v4.f32 [%0], {%1, %2, %3, %4};"
                 :: "l"(g_scr + cc.w), "f"(pD0), "f"(pD1), "f"(pD2), "f"(1.0f) : "memory");
}

// Node MLP + L2 normalize + re-zero scratch. FOUR nodes per thread.
__global__ void __launch_bounds__(256) node_kernel(
        const float* __restrict__ x,
        const float* __restrict__ w2a,
        const float* __restrict__ b2a,
        const float* __restrict__ w2b,
        const float* __restrict__ b2b,
        float* __restrict__ out) {
    // per hidden j: [w0..w5, bias, v0, v1, v2], duplicated. Row = 80B.
    __shared__ __align__(16) u64 sw[20][10];
    int t = threadIdx.x;
    if (t < 20) {
        sw[t][0] = pack2(w2a[t],           w2a[t]);
        sw[t][1] = pack2(w2a[20 + t],      w2a[20 + t]);
        sw[t][2] = pack2(w2a[40 + t],      w2a[40 + t]);
        sw[t][3] = pack2(w2a[60 + t],      w2a[60 + t]);
        sw[t][4] = pack2(w2a[80 + t],      w2a[80 + t]);
        sw[t][5] = pack2(w2a[100 + t],     w2a[100 + t]);
        sw[t][6] = pack2(b2a[t],           b2a[t]);
        sw[t][7] = pack2(w2b[3 * t],       w2b[3 * t]);
        sw[t][8] = pack2(w2b[3 * t + 1],   w2b[3 * t + 1]);
        sw[t][9] = pack2(w2b[3 * t + 2],   w2b[3 * t + 2]);
    }
    __syncthreads();

    int i = (blockIdx.x * 256 + t) * 4;
    if (i >= N_NODES) return;

    float4 sA = g_scr[i];
    float4 sB = g_scr[i + 1];
    float4 sC = g_scr[i + 2];
    float4 sD = g_scr[i + 3];
    const float4* px = (const float4*)(x + 3 * i);
    float4 xv0 = px[0];  // A.x A.y A.z B.x
    float4 xv1 = px[1];  // B.y B.z C.x C.y
    float4 xv2 = px[2];  // C.z D.x D.y D.z

    // Re-zero scratch for the next call.
    float4 z = make_float4(0.f, 0.f, 0.f, 0.f);
    g_scr[i]     = z;
    g_scr[i + 1] = z;
    g_scr[i + 2] = z;
    g_scr[i + 3] = z;

    float invA = 1.0f / fmaxf(sA.w, 1.0f);
    float invB = 1.0f / fmaxf(sB.w, 1.0f);
    float invC = 1.0f / fmaxf(sC.w, 1.0f);
    float invD = 1.0f / fmaxf(sD.w, 1.0f);

    u64 X0ab = pack2(xv0.x, xv0.w), X0cd = pack2(xv1.z, xv2.y);
    u64 X1ab = pack2(xv0.y, xv1.x), X1cd = pack2(xv1.w, xv2.z);
    u64 X2ab = pack2(xv0.z, xv1.y), X2cd = pack2(xv2.x, xv2.w);
    u64 A0ab = pack2(sA.x * invA, sB.x * invB), A0cd = pack2(sC.x * invC, sD.x * invD);
    u64 A1ab = pack2(sA.y * invA, sB.y * invB), A1cd = pack2(sC.y * invC, sD.y * invD);
    u64 A2ab = pack2(sA.z * invA, sB.z * invB), A2cd = pack2(sC.z * invC, sD.z * invD);

    float bb0 = b2b[0], bb1 = b2b[1], bb2 = b2b[2];
    u64 o0ab = pack2(bb0, bb0), o0cd = o0ab;
    u64 o1ab = pack2(bb1, bb1), o1cd = o1ab;
    u64 o2ab = pack2(bb2, bb2), o2cd = o2ab;

#pragma unroll
    for (int j = 0; j < 20; j++) {
        const u64* w = sw[j];
        // tree-form h: three parallel depth-2 branches + add tree
        u64 t1ab = fma2(X1ab, w[1], fma2(X0ab, w[0], w[6]));
        u64 t2ab = fma2(A0ab, w[3], mul2(X2ab, w[2]));
        u64 t3ab = fma2(A2ab, w[5], mul2(A1ab, w[4]));
        u64 t1cd = fma2(X1cd, w[1], fma2(X0cd, w[0], w[6]));
        u64 t2cd = fma2(A0cd, w[3], mul2(X2cd, w[2]));
        u64 t3cd = fma2(A2cd, w[5], mul2(A1cd, w[4]));
        u64 hab = relu2(add2(t1ab, add2(t2ab, t3ab)));
        u64 hcd = relu2(add2(t1cd, add2(t2cd, t3cd)));
        o0ab = fma2(hab, w[7], o0ab);  o0cd = fma2(hcd, w[7], o0cd);
        o1ab = fma2(hab, w[8], o1ab);  o1cd = fma2(hcd, w[8], o1cd);
        o2ab = fma2(hab, w[9], o2ab);  o2cd = fma2(hcd, w[9], o2cd);
    }

    float pA0, pB0, pA1, pB1, pA2, pB2;
    float pC0, pD0, pC1, pD1, pC2, pD2;
    unpack2(o0ab, pA0, pB0); unpack2(o1ab, pA1, pB1); unpack2(o2ab, pA2, pB2);
    unpack2(o0cd, pC0, pD0); unpack2(o1cd, pC1, pD1); unpack2(o2cd, pC2, pD2);

    float facA = rsqrtf(pA0 * pA0 + pA1 * pA1 + pA2 * pA2);
    float facB = rsqrtf(pB0 * pB0 + pB1 * pB1 + pB2 * pB2);
    float facC = rsqrtf(pC0 * pC0 + pC1 * pC1 + pC2 * pC2);
    float facD = rsqrtf(pD0 * pD0 + pD1 * pD1 + pD2 * pD2);

    float4* o = (float4*)(out + 3 * i);
    o[0] = make_float4(pA0 * facA, pA1 * facA, pA2 * facA, pB0 * facB);
    o[1] = make_float4(pB1 * facB, pB2 * facB, pC0 * facC, pC1 * facC);
    o[2] = make_float4(pC2 * facC, pD0 * facD, pD1 * facD, pD2 * facD);
}

extern "C" void kernel_launch(void* const* d_in, const int* in_sizes, int n_in,
                              void* d_out, int out_size) {
    // 0:x 1:edge_index 2:edge_attr 3:u 4:batch
    // 5:w1a 6:b1a 7:w1b 8:b1b 9:w2a 10:b2a 11:w2b 12:b2b
    const float* x     = (const float*)d_in[0];
    const int*   ei    = (const int*)  d_in[1];
    const float* eattr = (const float*)d_in[2];
    const float* w1a   = (const float*)d_in[5];
    const float* b1a   = (const float*)d_in[6];
    const float* w1b   = (const float*)d_in[7];
    const float* b1b   = (const float*)d_in[8];
    const float* w2a   = (const float*)d_in[9];
    const float* b2a   = (const float*)d_in[10];
    const float* w2b   = (const float*)d_in[11];
    const float* b2b   = (const float*)d_in[12];
    float* out = (float*)d_out;

    prep_kernel<<<N_NODES / 256, 256>>>((const float4*)x);
    edge_kernel<<<N_EDGES / 1024, 256>>>(ei, eattr, w1a, b1a, w1b, b1b);
    node_kernel<<<N_NODES / 1024, 256>>>(x, w2a, b2a, w2b, b2b, out);
}

// round 9
// speedup vs baseline: 1.0603x; 1.0603x over previous
#include <cuda_runtime.h>

#define N_NODES 1048576
#define N_EDGES (4 * N_NODES)

typedef unsigned long long u64;

// Scratch accumulator: per-node (sum0,sum1,sum2,count). Zeroed by prep_kernel
// at the start of every call (zero-init at load makes call 0 identical).
__device__ float4 g_scr[N_NODES];
// Padded x table: one 16B row per node -> single-wavefront gathers.
__device__ float4 g_x4[N_NODES];

__device__ __forceinline__ u64 fma2(u64 a, u64 b, u64 c) {
    u64 d;
    asm("fma.rn.f32x2 %0, %1, %2, %3;" : "=l"(d) : "l"(a), "l"(b), "l"(c));
    return d;
}
__device__ __forceinline__ u64 pack2(float lo, float hi) {
    u64 d;
    asm("mov.b64 %0, {%1, %2};" : "=l"(d) : "f"(lo), "f"(hi));
    return d;
}
__device__ __forceinline__ void unpack2(u64 a, float& lo, float& hi) {
    asm("mov.b64 {%0, %1}, %2;" : "=f"(lo), "=f"(hi) : "l"(a));
}
__device__ __forceinline__ u64 relu2(u64 a) {
    float lo, hi;
    unpack2(a, lo, hi);
    return pack2(fmaxf(lo, 0.f), fmaxf(hi, 0.f));
}

// Pad x[N,3] -> g_x4 via smem transpose, and zero g_scr. One node per thread.
__global__ void __launch_bounds__(256) prep_kernel(const float4* __restrict__ x) {
    __shared__ float sx[768];
    int t = threadIdx.x;
    if (t < 192) {
        float4 v = x[blockIdx.x * 192 + t];
        *(float4*)&sx[4 * t] = v;
    }
    __syncthreads();
    int node = blockIdx.x * 256 + t;
    // stride-3 float reads: 3 coprime to 32 banks -> conflict-free
    g_x4[node] = make_float4(sx[3 * t], sx[3 * t + 1], sx[3 * t + 2], 0.f);
    g_scr[node] = make_float4(0.f, 0.f, 0.f, 0.f);
}

// Edge MLP + scatter-add. FOUR edges per thread, two packed f32x2 streams.
__global__ void __launch_bounds__(256) edge_kernel(
        const int*   __restrict__ ei,
        const float* __restrict__ eattr,
        const float* __restrict__ w1a,
        const float* __restrict__ b1a,
        const float* __restrict__ w1b,
        const float* __restrict__ b1b) {
    // per hidden j: [wx, wy, wz, ww, bias, v0, v1, v2], each scalar duplicated.
    __shared__ __align__(16) u64 sw[20][8];
    int t = threadIdx.x;
    if (t < 20) {
        sw[t][0] = pack2(w1a[t],          w1a[t]);
        sw[t][1] = pack2(w1a[20 + t],     w1a[20 + t]);
        sw[t][2] = pack2(w1a[40 + t],     w1a[40 + t]);
        sw[t][3] = pack2(w1a[60 + t],     w1a[60 + t]);
        sw[t][4] = pack2(b1a[t],          b1a[t]);
        sw[t][5] = pack2(w1b[3 * t],      w1b[3 * t]);
        sw[t][6] = pack2(w1b[3 * t + 1],  w1b[3 * t + 1]);
        sw[t][7] = pack2(w1b[3 * t + 2],  w1b[3 * t + 2]);
    }
    __syncthreads();

    int e = (blockIdx.x * 256 + t) * 4;
    if (e >= N_EDGES) return;

    int4   rr = *(const int4*)(ei + e);             // source nodes A,B,C,D
    int4   cc = *(const int4*)(ei + N_EDGES + e);   // destination nodes
    float4 ef = *(const float4*)(eattr + e);

    // 4 single-wavefront gathers issued back-to-back.
    float4 xa = __ldg(&g_x4[rr.x]);
    float4 xb = __ldg(&g_x4[rr.y]);
    float4 xc = __ldg(&g_x4[rr.z]);
    float4 xd = __ldg(&g_x4[rr.w]);

    u64 X0ab = pack2(xa.x, xb.x), X0cd = pack2(xc.x, xd.x);
    u64 X1ab = pack2(xa.y, xb.y), X1cd = pack2(xc.y, xd.y);
    u64 X2ab = pack2(xa.z, xb.z), X2cd = pack2(xc.z, xd.z);
    u64 EAab = pack2(ef.x, ef.y), EAcd = pack2(ef.z, ef.w);

    float bb0 = b1b[0], bb1 = b1b[1], bb2 = b1b[2];
    u64 o0ab = pack2(bb0, bb0), o0cd = o0ab;
    u64 o1ab = pack2(bb1, bb1), o1cd = o1ab;
    u64 o2ab = pack2(bb2, bb2), o2cd = o2ab;

#pragma unroll
    for (int j = 0; j < 20; j++) {
        const u64* w = sw[j];
        u64 hab = fma2(X0ab, w[0], fma2(X1ab, w[1], fma2(X2ab, w[2], fma2(EAab, w[3], w[4]))));
        u64 hcd = fma2(X0cd, w[0], fma2(X1cd, w[1], fma2(X2cd, w[2], fma2(EAcd, w[3], w[4]))));
        hab = relu2(hab);
        hcd = relu2(hcd);
        o0ab = fma2(hab, w[5], o0ab);  o0cd = fma2(hcd, w[5], o0cd);
        o1ab = fma2(hab, w[6], o1ab);  o1cd = fma2(hcd, w[6], o1cd);
        o2ab = fma2(hab, w[7], o2ab);  o2cd = fma2(hcd, w[7], o2cd);
    }

    float pA0, pB0, pA1, pB1, pA2, pB2;
    float pC0, pD0, pC1, pD1, pC2, pD2;
    unpack2(o0ab, pA0, pB0); unpack2(o1ab, pA1, pB1); unpack2(o2ab, pA2, pB2);
    unpack2(o0cd, pC0, pD0); unpack2(o1cd, pC1, pD1); unpack2(o2cd, pC2, pD2);

    asm volatile("red.global.add.v4.f32 [%0], {%1, %2, %3, %4};"
                 :: "l"(g_scr + cc.x), "f"(pA0), "f"(pA1), "f"(pA2), "f"(1.0f) : "memory");
    asm volatile("red.global.add.v4.f32 [%0], {%1, %2, %3, %4};"
                 :: "l"(g_scr + cc.y), "f"(pB0), "f"(pB1), "f"(pB2), "f"(1.0f) : "memory");
    asm volatile("red.global.add.v4.f32 [%0], {%1, %2, %3, %4};"
                 :: "l"(g_scr + cc.z), "f"(pC0), "f"(pC1), "f"(pC2), "f"(1.0f) : "memory");
    asm volatile("red.global.add.v4.f32 [%0], {%1, %2, %3, %4};"
                 :: "l"(g_scr + cc.w), "f"(pD0), "f"(pD1), "f"(pD2), "f"(1.0f) : "memory");
}

// Node MLP + L2 normalize. FOUR nodes per thread.
// __launch_bounds__(256, 4): cap regs at 64 to get 4 blocks/SM (occ ~50%).
__global__ void __launch_bounds__(256, 4) node_kernel(
        const float* __restrict__ x,
        const float* __restrict__ w2a,
        const float* __restrict__ b2a,
        const float* __restrict__ w2b,
        const float* __restrict__ b2b,
        float* __restrict__ out) {
    // per hidden j: [w0..w5, bias, v0, v1, v2], duplicated. Row = 80B.
    __shared__ __align__(16) u64 sw[20][10];
    int t = threadIdx.x;
    if (t < 20) {
        sw[t][0] = pack2(w2a[t],           w2a[t]);
        sw[t][1] = pack2(w2a[20 + t],      w2a[20 + t]);
        sw[t][2] = pack2(w2a[40 + t],      w2a[40 + t]);
        sw[t][3] = pack2(w2a[60 + t],      w2a[60 + t]);
        sw[t][4] = pack2(w2a[80 + t],      w2a[80 + t]);
        sw[t][5] = pack2(w2a[100 + t],     w2a[100 + t]);
        sw[t][6] = pack2(b2a[t],           b2a[t]);
        sw[t][7] = pack2(w2b[3 * t],       w2b[3 * t]);
        sw[t][8] = pack2(w2b[3 * t + 1],   w2b[3 * t + 1]);
        sw[t][9] = pack2(w2b[3 * t + 2],   w2b[3 * t + 2]);
    }
    __syncthreads();

    int i = (blockIdx.x * 256 + t) * 4;
    if (i >= N_NODES) return;

    float4 sA = g_scr[i];
    float4 sB = g_scr[i + 1];
    float4 sC = g_scr[i + 2];
    float4 sD = g_scr[i + 3];
    const float4* px = (const float4*)(x + 3 * i);
    float4 xv0 = px[0];  // A.x A.y A.z B.x
    float4 xv1 = px[1];  // B.y B.z C.x C.y
    float4 xv2 = px[2];  // C.z D.x D.y D.z

    float invA = 1.0f / fmaxf(sA.w, 1.0f);
    float invB = 1.0f / fmaxf(sB.w, 1.0f);
    float invC = 1.0f / fmaxf(sC.w, 1.0f);
    float invD = 1.0f / fmaxf(sD.w, 1.0f);

    u64 X0ab = pack2(xv0.x, xv0.w), X0cd = pack2(xv1.z, xv2.y);
    u64 X1ab = pack2(xv0.y, xv1.x), X1cd = pack2(xv1.w, xv2.z);
    u64 X2ab = pack2(xv0.z, xv1.y), X2cd = pack2(xv2.x, xv2.w);
    u64 A0ab = pack2(sA.x * invA, sB.x * invB), A0cd = pack2(sC.x * invC, sD.x * invD);
    u64 A1ab = pack2(sA.y * invA, sB.y * invB), A1cd = pack2(sC.y * invC, sD.y * invD);
    u64 A2ab = pack2(sA.z * invA, sB.z * invB), A2cd = pack2(sC.z * invC, sD.z * invD);

    float bb0 = b2b[0], bb1 = b2b[1], bb2 = b2b[2];
    u64 o0ab = pack2(bb0, bb0), o0cd = o0ab;
    u64 o1ab = pack2(bb1, bb1), o1cd = o1ab;
    u64 o2ab = pack2(bb2, bb2), o2cd = o2ab;

#pragma unroll
    for (int j = 0; j < 20; j++) {
        const u64* w = sw[j];
        u64 hab = fma2(X0ab, w[0],
                  fma2(X1ab, w[1],
                  fma2(X2ab, w[2],
                  fma2(A0ab, w[3],
                  fma2(A1ab, w[4],
                  fma2(A2ab, w[5], w[6]))))));
        u64 hcd = fma2(X0cd, w[0],
                  fma2(X1cd, w[1],
                  fma2(X2cd, w[2],
                  fma2(A0cd, w[3],
                  fma2(A1cd, w[4],
                  fma2(A2cd, w[5], w[6]))))));
        hab = relu2(hab);
        hcd = relu2(hcd);
        o0ab = fma2(hab, w[7], o0ab);  o0cd = fma2(hcd, w[7], o0cd);
        o1ab = fma2(hab, w[8], o1ab);  o1cd = fma2(hcd, w[8], o1cd);
        o2ab = fma2(hab, w[9], o2ab);  o2cd = fma2(hcd, w[9], o2cd);
    }

    float pA0, pB0, pA1, pB1, pA2, pB2;
    float pC0, pD0, pC1, pD1, pC2, pD2;
    unpack2(o0ab, pA0, pB0); unpack2(o1ab, pA1, pB1); unpack2(o2ab, pA2, pB2);
    unpack2(o0cd, pC0, pD0); unpack2(o1cd, pC1, pD1); unpack2(o2cd, pC2, pD2);

    float facA = rsqrtf(pA0 * pA0 + pA1 * pA1 + pA2 * pA2);
    float facB = rsqrtf(pB0 * pB0 + pB1 * pB1 + pB2 * pB2);
    float facC = rsqrtf(pC0 * pC0 + pC1 * pC1 + pC2 * pC2);
    float facD = rsqrtf(pD0 * pD0 + pD1 * pD1 + pD2 * pD2);

    float4* o = (float4*)(out + 3 * i);
    o[0] = make_float4(pA0 * facA, pA1 * facA, pA2 * facA, pB0 * facB);
    o[1] = make_float4(pB1 * facB, pB2 * facB, pC0 * facC, pC1 * facC);
    o[2] = make_float4(pC2 * facC, pD0 * facD, pD1 * facD, pD2 * facD);
}

extern "C" void kernel_launch(void* const* d_in, const int* in_sizes, int n_in,
                              void* d_out, int out_size) {
    // 0:x 1:edge_index 2:edge_attr 3:u 4:batch
    // 5:w1a 6:b1a 7:w1b 8:b1b 9:w2a 10:b2a 11:w2b 12:b2b
    const float* x     = (const float*)d_in[0];
    const int*   ei    = (const int*)  d_in[1];
    const float* eattr = (const float*)d_in[2];
    const float* w1a   = (const float*)d_in[5];
    const float* b1a   = (const float*)d_in[6];
    const float* w1b   = (const float*)d_in[7];
    const float* b1b   = (const float*)d_in[8];
    const float* w2a   = (const float*)d_in[9];
    const float* b2a   = (const float*)d_in[10];
    const float* w2b   = (const float*)d_in[11];
    const float* b2b   = (const float*)d_in[12];
    float* out = (float*)d_out;

    prep_kernel<<<N_NODES / 256, 256>>>((const float4*)x);
    edge_kernel<<<N_EDGES / 1024, 256>>>(ei, eattr, w1a, b1a, w1b, b1b);
    node_kernel<<<N_NODES / 1024, 256>>>(x, w2a, b2a, w2b, b2b, out);
}